// round 4
// baseline (speedup 1.0000x reference)
#include <cuda_runtime.h>
#include <cstdint>

// Problem constants
#define BATCH 2048
#define SEQ   64
#define DIMM  512
#define HEADS 8
#define DHEAD 64
#define INNER 512
#define M_ROWS (BATCH * SEQ)          // 131072
#define OUT_ELEMS ((long long)M_ROWS * DIMM)  // 67108864

// Scratch (allocation-free rule: __device__ globals)
__device__ float g_q[(size_t)M_ROWS * INNER];
__device__ float g_k[(size_t)M_ROWS * INNER];
__device__ float g_v[(size_t)M_ROWS * INNER];
__device__ float g_att[(size_t)M_ROWS * INNER];

// ---------------------------------------------------------------------------
// TF32 helpers
// ---------------------------------------------------------------------------
__device__ __forceinline__ unsigned f2tf32(float f) {
    unsigned r;
    asm("cvt.rna.tf32.f32 %0, %1;" : "=r"(r) : "f"(f));
    return r;
}

__device__ __forceinline__ void mma_tf32(float c[4], const unsigned a[4],
                                         unsigned b0, unsigned b1) {
    asm volatile(
        "mma.sync.aligned.m16n8k8.row.col.f32.tf32.tf32.f32 "
        "{%0,%1,%2,%3}, {%4,%5,%6,%7}, {%8,%9}, {%0,%1,%2,%3};\n"
        : "+f"(c[0]), "+f"(c[1]), "+f"(c[2]), "+f"(c[3])
        : "r"(a[0]), "r"(a[1]), "r"(a[2]), "r"(a[3]), "r"(b0), "r"(b1));
}

// ---------------------------------------------------------------------------
// GEMM: C[M,512] = A[M,512] * W[512,512] + bias   (TF32 tensor cores)
// Tile 128x128x32, 256 threads = 8 warps (4x2), warp tile 32x64.
// mode 0: A = X (input x), C selected by blockIdx.z -> g_q/g_k/g_v
// mode 1: A = g_att, C = Cout
// ---------------------------------------------------------------------------
#define BM 128
#define BN 128
#define BK 32
#define AP 36    // pitch for As: (4*row + k) mod 32 distinct -> conflict-free frag reads
#define BP 136   // pitch for Bs: (8*k + n) mod 32 distinct -> conflict-free frag reads

__global__ __launch_bounds__(256, 2)
void gemm_tf32_bias(const float* __restrict__ X,
                    const float* __restrict__ W0, const float* __restrict__ W1,
                    const float* __restrict__ W2,
                    const float* __restrict__ bias0, const float* __restrict__ bias1,
                    const float* __restrict__ bias2,
                    float* __restrict__ Cout, int mode)
{
    const float* Asrc;
    const float* W;
    const float* bias;
    float* C;
    if (mode == 0) {
        Asrc = X;
        if (blockIdx.z == 0)      { W = W0; bias = bias0; C = g_q; }
        else if (blockIdx.z == 1) { W = W1; bias = bias1; C = g_k; }
        else                      { W = W2; bias = bias2; C = g_v; }
    } else {
        Asrc = g_att; W = W0; bias = bias0; C = Cout;
    }

    __shared__ unsigned As[BM][AP];
    __shared__ unsigned Bs[BK][BP];

    const int t  = threadIdx.x;
    const int m0 = blockIdx.y * BM;
    const int n0 = blockIdx.x * BN;

    // global-load mappings (coalesced float4)
    const int ar = t >> 3;            // 0..31 (A tile row base)
    const int ac = (t & 7) * 4;       // 0..28 (A tile col, float4)
    const int br = t >> 5;            // 0..7  (B tile row base)
    const int bc = (t & 31) * 4;      // 0..124 (B tile col, float4)

    const int w    = t >> 5;
    const int lane = t & 31;
    const int gid  = lane >> 2;       // 0..7
    const int tig  = lane & 3;        // 0..3
    const int wm   = (w & 3) * 32;    // warp M offset in tile
    const int wn   = (w >> 2) * 64;   // warp N offset in tile

    float acc[2][8][4];
#pragma unroll
    for (int mi = 0; mi < 2; mi++)
#pragma unroll
        for (int nj = 0; nj < 8; nj++)
#pragma unroll
            for (int c = 0; c < 4; c++) acc[mi][nj][c] = 0.0f;

    float4 areg[4], breg[4];
    // prologue: load kt=0
#pragma unroll
    for (int i = 0; i < 4; i++)
        areg[i] = *(const float4*)(Asrc + (size_t)(m0 + ar + 32 * i) * 512 + ac);
#pragma unroll
    for (int i = 0; i < 4; i++)
        breg[i] = *(const float4*)(W + (size_t)(br + 8 * i) * 512 + n0 + bc);

    for (int kt = 0; kt < 16; kt++) {
        __syncthreads();
        // stage regs -> smem (convert to tf32, vectorized stores; pitches keep 16B alignment)
#pragma unroll
        for (int i = 0; i < 4; i++) {
            uint4 u = make_uint4(f2tf32(areg[i].x), f2tf32(areg[i].y),
                                 f2tf32(areg[i].z), f2tf32(areg[i].w));
            *(uint4*)&As[ar + 32 * i][ac] = u;
        }
#pragma unroll
        for (int i = 0; i < 4; i++) {
            uint4 u = make_uint4(f2tf32(breg[i].x), f2tf32(breg[i].y),
                                 f2tf32(breg[i].z), f2tf32(breg[i].w));
            *(uint4*)&Bs[br + 8 * i][bc] = u;
        }
        __syncthreads();

        // prefetch next tile (overlaps the MMA work below)
        if (kt < 15) {
            const int kc = (kt + 1) * 32;
#pragma unroll
            for (int i = 0; i < 4; i++)
                areg[i] = *(const float4*)(Asrc + (size_t)(m0 + ar + 32 * i) * 512 + kc + ac);
#pragma unroll
            for (int i = 0; i < 4; i++)
                breg[i] = *(const float4*)(W + (size_t)(kc + br + 8 * i) * 512 + n0 + bc);
        }

#pragma unroll
        for (int ks = 0; ks < 4; ks++) {
            const int k0 = ks * 8;
            unsigned a[2][4];
#pragma unroll
            for (int mi = 0; mi < 2; mi++) {
                const int row = wm + mi * 16 + gid;
                a[mi][0] = As[row][k0 + tig];
                a[mi][1] = As[row + 8][k0 + tig];
                a[mi][2] = As[row][k0 + 4 + tig];
                a[mi][3] = As[row + 8][k0 + 4 + tig];
            }
#pragma unroll
            for (int nj = 0; nj < 8; nj++) {
                const int col = wn + nj * 8 + gid;
                const unsigned bb0 = Bs[k0 + tig][col];
                const unsigned bb1 = Bs[k0 + 4 + tig][col];
                mma_tf32(acc[0][nj], a[0], bb0, bb1);
                mma_tf32(acc[1][nj], a[1], bb0, bb1);
            }
        }
    }

    // epilogue: bias + store (float2, coalesced within warps)
#pragma unroll
    for (int mi = 0; mi < 2; mi++) {
#pragma unroll
        for (int nj = 0; nj < 8; nj++) {
            const int row = m0 + wm + mi * 16 + gid;
            const int col = n0 + wn + nj * 8 + tig * 2;
            const float2 bv = *(const float2*)(bias + col);
            float2 o01 = make_float2(acc[mi][nj][0] + bv.x, acc[mi][nj][1] + bv.y);
            float2 o23 = make_float2(acc[mi][nj][2] + bv.x, acc[mi][nj][3] + bv.y);
            *(float2*)(C + (size_t)row * 512 + col)       = o01;
            *(float2*)(C + (size_t)(row + 8) * 512 + col) = o23;
        }
    }
}

// ---------------------------------------------------------------------------
// Attention: one block per (b, h). 256 threads as 16x16, each computes a 4x4
// tile of S (then O). q row-major in sA, k TRANSPOSED (d-major) in sB so the
// S inner loop reads both operands conflict-free. After softmax, sA holds P
// and sB is reloaded with V (row-major).
// ---------------------------------------------------------------------------
__global__ __launch_bounds__(256)
void attn_kernel(const float* __restrict__ mask)
{
    __shared__ float sA[64][68];  // q, then P
    __shared__ float sB[64][68];  // k^T, then V

    const int b = blockIdx.y;
    const int h = blockIdx.x;
    const int t = threadIdx.x;
    const size_t base = ((size_t)b * 64) * 512 + (size_t)h * 64;

    // load q (row-major) and k (transposed)
#pragma unroll
    for (int i = 0; i < 4; i++) {
        const int idx = t + 256 * i;
        const int row = idx >> 4;
        const int c4  = (idx & 15) * 4;
        float4 qv = *(const float4*)(g_q + base + (size_t)row * 512 + c4);
        *(float4*)&sA[row][c4] = qv;
        float4 kv = *(const float4*)(g_k + base + (size_t)row * 512 + c4);
        sB[c4 + 0][row] = kv.x;
        sB[c4 + 1][row] = kv.y;
        sB[c4 + 2][row] = kv.z;
        sB[c4 + 3][row] = kv.w;
    }
    __syncthreads();

    const int ty = t >> 4, tx = t & 15;
    const int i0 = ty * 4, j0 = tx * 4;

    // S = Q K^T  (registers, 4x4 per thread)
    float acc[4][4];
#pragma unroll
    for (int r = 0; r < 4; r++)
#pragma unroll
        for (int c = 0; c < 4; c++) acc[r][c] = 0.0f;

#pragma unroll
    for (int d = 0; d < 64; d += 4) {
        float kc[4][4];
#pragma unroll
        for (int dd = 0; dd < 4; dd++) {
            float4 kv = *(const float4*)&sB[d + dd][j0];
            kc[dd][0] = kv.x; kc[dd][1] = kv.y; kc[dd][2] = kv.z; kc[dd][3] = kv.w;
        }
#pragma unroll
        for (int r = 0; r < 4; r++) {
            float4 qv = *(const float4*)&sA[i0 + r][d];
#pragma unroll
            for (int c = 0; c < 4; c++) {
                acc[r][c] += qv.x * kc[0][c] + qv.y * kc[1][c] +
                             qv.z * kc[2][c] + qv.w * kc[3][c];
            }
        }
    }

    // masked softmax per row: rows live across the 16 tx lanes of each warp half
    const float* mrow = mask + ((size_t)b * 64) * 64;
    float p[4][4];
#pragma unroll
    for (int r = 0; r < 4; r++) {
        float4 mv = *(const float4*)(mrow + (size_t)(i0 + r) * 64 + j0);
        float s0 = acc[r][0] * 0.125f + __logf(mv.x + 1e-9f);
        float s1 = acc[r][1] * 0.125f + __logf(mv.y + 1e-9f);
        float s2 = acc[r][2] * 0.125f + __logf(mv.z + 1e-9f);
        float s3 = acc[r][3] * 0.125f + __logf(mv.w + 1e-9f);
        float mx = fmaxf(fmaxf(s0, s1), fmaxf(s2, s3));
        mx = fmaxf(mx, __shfl_xor_sync(0xffffffffu, mx, 1));
        mx = fmaxf(mx, __shfl_xor_sync(0xffffffffu, mx, 2));
        mx = fmaxf(mx, __shfl_xor_sync(0xffffffffu, mx, 4));
        mx = fmaxf(mx, __shfl_xor_sync(0xffffffffu, mx, 8));
        float e0 = __expf(s0 - mx);
        float e1 = __expf(s1 - mx);
        float e2 = __expf(s2 - mx);
        float e3 = __expf(s3 - mx);
        float sum = e0 + e1 + e2 + e3;
        sum += __shfl_xor_sync(0xffffffffu, sum, 1);
        sum += __shfl_xor_sync(0xffffffffu, sum, 2);
        sum += __shfl_xor_sync(0xffffffffu, sum, 4);
        sum += __shfl_xor_sync(0xffffffffu, sum, 8);
        const float inv = 1.0f / sum;
        p[r][0] = e0 * inv; p[r][1] = e1 * inv; p[r][2] = e2 * inv; p[r][3] = e3 * inv;
    }

    __syncthreads();  // everyone done reading sA/sB before overwrite

    // P -> sA, V -> sB (row-major)
#pragma unroll
    for (int r = 0; r < 4; r++)
        *(float4*)&sA[i0 + r][j0] = make_float4(p[r][0], p[r][1], p[r][2], p[r][3]);
#pragma unroll
    for (int i = 0; i < 4; i++) {
        const int idx = t + 256 * i;
        const int row = idx >> 4;
        const int c4  = (idx & 15) * 4;
        *(float4*)&sB[row][c4] = *(const float4*)(g_v + base + (size_t)row * 512 + c4);
    }
    __syncthreads();

    // O = P V
    float o[4][4];
#pragma unroll
    for (int r = 0; r < 4; r++)
#pragma unroll
        for (int c = 0; c < 4; c++) o[r][c] = 0.0f;

#pragma unroll
    for (int j = 0; j < 64; j += 4) {
        float vc[4][4];
#pragma unroll
        for (int jj = 0; jj < 4; jj++) {
            float4 vv = *(const float4*)&sB[j + jj][j0];
            vc[jj][0] = vv.x; vc[jj][1] = vv.y; vc[jj][2] = vv.z; vc[jj][3] = vv.w;
        }
#pragma unroll
        for (int r = 0; r < 4; r++) {
            float4 pv = *(const float4*)&sA[i0 + r][j];
#pragma unroll
            for (int c = 0; c < 4; c++) {
                o[r][c] += pv.x * vc[0][c] + pv.y * vc[1][c] +
                           pv.z * vc[2][c] + pv.w * vc[3][c];
            }
        }
    }

#pragma unroll
    for (int r = 0; r < 4; r++) {
        *(float4*)(g_att + base + (size_t)(i0 + r) * 512 + j0) =
            make_float4(o[r][0], o[r][1], o[r][2], o[r][3]);
    }
}

// ---------------------------------------------------------------------------
// Zero-fill trailing output elements (the ccd_loss scalar == 0.0)
// ---------------------------------------------------------------------------
__global__ void tail_zero(float* __restrict__ out, long long start, long long total)
{
    long long i = start + (long long)blockIdx.x * blockDim.x + threadIdx.x;
    if (i < total) out[i] = 0.0f;
}

// ---------------------------------------------------------------------------
// kernel_launch
// ---------------------------------------------------------------------------
extern "C" void kernel_launch(void* const* d_in, const int* in_sizes, int n_in,
                              void* d_out, int out_size)
{
    const float* x    = (const float*)d_in[0];
    const float* mask = (const float*)d_in[1];
    const float* Wq   = (const float*)d_in[2];
    const float* bq   = (const float*)d_in[3];
    const float* Wk   = (const float*)d_in[4];
    const float* bk   = (const float*)d_in[5];
    const float* Wv   = (const float*)d_in[6];
    const float* bv   = (const float*)d_in[7];
    const float* Wo   = (const float*)d_in[8];
    const float* bo   = (const float*)d_in[9];
    float* out = (float*)d_out;

    // 1) Fused QKV projections (TF32 MMA), z selects q/k/v
    gemm_tf32_bias<<<dim3(512 / BN, M_ROWS / BM, 3), 256>>>(
        x, Wq, Wk, Wv, bq, bk, bv, nullptr, 0);

    // 2) Channel-masked attention, one block per (b, h)
    attn_kernel<<<dim3(HEADS, BATCH), 256>>>(mask);

    // 3) Output projection
    gemm_tf32_bias<<<dim3(512 / BN, M_ROWS / BM, 1), 256>>>(
        nullptr, Wo, Wo, Wo, bo, bo, bo, out, 1);

    // 4) Tail (ccd_loss scalar and any padding) = 0
    long long tail = (long long)out_size - OUT_ELEMS;
    if (tail > 0) {
        int blocks = (int)((tail + 255) / 256);
        tail_zero<<<blocks, 256>>>(out, OUT_ELEMS, (long long)out_size);
    }
}